// round 2
// baseline (speedup 1.0000x reference)
#include <cuda_runtime.h>
#include <cstdint>

// Problem constants
#define BATCH 4
#define HW    16384
#define CDIM  256
#define HEADS 8
#define DH    32

// Scratch (device globals; no allocations allowed)
__device__ float g_G[BATCH * CDIM * CDIM];     // Gram per batch
__device__ float g_Yq[BATCH * CDIM * CDIM];    // G @ Wq
__device__ float g_Yk[BATCH * CDIM * CDIM];    // G @ Wk
__device__ float g_Mm[BATCH * CDIM * CDIM];    // Wq^T G Wk
__device__ float g_dq[BATCH * CDIM];           // diag(Wq^T G Wq)
__device__ float g_dk[BATCH * CDIM];           // diag(Wk^T G Wk)
__device__ float g_attn[BATCH * HEADS * DH * DH];
__device__ float g_Wmix[BATCH * CDIM * CDIM];  // blockdiag(attn^T) @ Wout
__device__ float g_Weff[BATCH * CDIM * CDIM];  // Wv @ Wmix

__device__ __forceinline__ uint32_t f2tf(float x) {
    uint32_t r;
    asm("cvt.rna.tf32.f32 %0, %1;" : "=r"(r) : "f"(x));
    return r;
}

__device__ __forceinline__ void mma8(float* c, const uint32_t* a, const uint32_t* b) {
    asm volatile(
        "mma.sync.aligned.m16n8k8.row.col.f32.tf32.tf32.f32 "
        "{%0,%1,%2,%3}, {%4,%5,%6,%7}, {%8,%9}, {%0,%1,%2,%3};"
        : "+f"(c[0]), "+f"(c[1]), "+f"(c[2]), "+f"(c[3])
        : "r"(a[0]), "r"(a[1]), "r"(a[2]), "r"(a[3]), "r"(b[0]), "r"(b[1]));
}

// ---------------------------------------------------------------------------
// Generic tf32 GEMM, 128x128 CTA tile, 256 threads (8 warps in 2x4 grid,
// warp tile 64x32 = 4x4 m16n8k8 fragments).
//
//  TA=true :  C[m][n] = sum_k A[k][m] * B[k][n]   (A is KxM row-major)
//  TA=false:  C[m][n] = sum_k A[m][k] * B[k][n]   (A is MxK row-major)
//  ATOMIC  :  atomicAdd epilogue (split-K), else plain store.
//
// All dims must be multiples of 128 (M,N) and 32 (K). Verified for this
// problem (256 / 16384 everywhere).
// ---------------------------------------------------------------------------
template <bool TA, bool ATOMIC>
__global__ __launch_bounds__(256) void gemm_tf32(
    const float* __restrict__ Ag, const float* __restrict__ Bg,
    float* __restrict__ Cg, int Mdim, int Ndim, int Kdim,
    long sA, long sB, long sC, int kChunk)
{
    const int tilesN = Ndim >> 7;
    const int tilesM = Mdim >> 7;
    const int tileCount = tilesM * tilesN;
    const int tileId = blockIdx.x % tileCount;
    const int split  = blockIdx.x / tileCount;
    const int tm = tileId / tilesN;
    const int tn = tileId % tilesN;

    const float* A = Ag + (long)blockIdx.z * sA;
    const float* Bp = Bg + (long)blockIdx.z * sB;
    float* Cp = Cg + (long)blockIdx.z * sC;

    const int k0 = split * kChunk;
    const int k1 = k0 + kChunk;

    // TA:  Asm[k][m] with stride 136  (32*136 = 4352)
    // !TA: Asm[m][k] with stride 36   (128*36 = 4608)
    __shared__ uint32_t Asm[4608];
    __shared__ uint32_t Bsm[4352];   // Bsm[k][n] stride 136

    const int tid  = threadIdx.x;
    const int lane = tid & 31;
    const int warp = tid >> 5;
    const int wm = warp >> 2;        // 0..1
    const int wn = warp & 3;         // 0..3
    const int g  = lane >> 2;        // 0..7
    const int t4 = lane & 3;         // 0..3

    float acc[4][4][4];
#pragma unroll
    for (int i = 0; i < 4; i++)
#pragma unroll
        for (int j = 0; j < 4; j++)
#pragma unroll
            for (int r = 0; r < 4; r++) acc[i][j][r] = 0.f;

    for (int kk = k0; kk < k1; kk += 32) {
        // ---- load A tile ----
        if (TA) {
#pragma unroll
            for (int r = 0; r < 4; r++) {
                int idx = tid + r * 256;        // 1024 float4: 32 k x 32 m-quads
                int k   = idx >> 5;
                int m4  = (idx & 31) << 2;
                float4 v = *(const float4*)(A + (long)(kk + k) * Mdim + (tm << 7) + m4);
                Asm[k * 136 + m4 + 0] = f2tf(v.x);
                Asm[k * 136 + m4 + 1] = f2tf(v.y);
                Asm[k * 136 + m4 + 2] = f2tf(v.z);
                Asm[k * 136 + m4 + 3] = f2tf(v.w);
            }
        } else {
#pragma unroll
            for (int r = 0; r < 4; r++) {
                int idx = tid + r * 256;        // 1024 float4: 128 m x 8 k-quads
                int m   = idx >> 3;
                int k4  = (idx & 7) << 2;
                float4 v = *(const float4*)(A + (long)((tm << 7) + m) * Kdim + kk + k4);
                Asm[m * 36 + k4 + 0] = f2tf(v.x);
                Asm[m * 36 + k4 + 1] = f2tf(v.y);
                Asm[m * 36 + k4 + 2] = f2tf(v.z);
                Asm[m * 36 + k4 + 3] = f2tf(v.w);
            }
        }
        // ---- load B tile ----
#pragma unroll
        for (int r = 0; r < 4; r++) {
            int idx = tid + r * 256;
            int k   = idx >> 5;
            int n4  = (idx & 31) << 2;
            float4 v = *(const float4*)(Bp + (long)(kk + k) * Ndim + (tn << 7) + n4);
            Bsm[k * 136 + n4 + 0] = f2tf(v.x);
            Bsm[k * 136 + n4 + 1] = f2tf(v.y);
            Bsm[k * 136 + n4 + 2] = f2tf(v.z);
            Bsm[k * 136 + n4 + 3] = f2tf(v.w);
        }
        __syncthreads();

#pragma unroll
        for (int ks = 0; ks < 32; ks += 8) {
            uint32_t af[4][4], bf[4][2];
#pragma unroll
            for (int mi = 0; mi < 4; mi++) {
                int m0 = wm * 64 + mi * 16;
                if (TA) {
                    af[mi][0] = Asm[(ks + t4) * 136 + m0 + g];
                    af[mi][1] = Asm[(ks + t4) * 136 + m0 + g + 8];
                    af[mi][2] = Asm[(ks + t4 + 4) * 136 + m0 + g];
                    af[mi][3] = Asm[(ks + t4 + 4) * 136 + m0 + g + 8];
                } else {
                    af[mi][0] = Asm[(m0 + g) * 36 + ks + t4];
                    af[mi][1] = Asm[(m0 + g + 8) * 36 + ks + t4];
                    af[mi][2] = Asm[(m0 + g) * 36 + ks + t4 + 4];
                    af[mi][3] = Asm[(m0 + g + 8) * 36 + ks + t4 + 4];
                }
            }
#pragma unroll
            for (int ni = 0; ni < 4; ni++) {
                int n0 = wn * 32 + ni * 8;
                bf[ni][0] = Bsm[(ks + t4) * 136 + n0 + g];
                bf[ni][1] = Bsm[(ks + t4 + 4) * 136 + n0 + g];
            }
#pragma unroll
            for (int mi = 0; mi < 4; mi++)
#pragma unroll
                for (int ni = 0; ni < 4; ni++)
                    mma8(acc[mi][ni], af[mi], bf[ni]);
        }
        __syncthreads();
    }

    // ---- epilogue ----
#pragma unroll
    for (int mi = 0; mi < 4; mi++) {
#pragma unroll
        for (int ni = 0; ni < 4; ni++) {
            int row = (tm << 7) + wm * 64 + mi * 16 + g;
            int col = (tn << 7) + wn * 32 + ni * 8 + t4 * 2;
            float* p = Cp + (long)row * Ndim + col;
            if (ATOMIC) {
                atomicAdd(p,                acc[mi][ni][0]);
                atomicAdd(p + 1,            acc[mi][ni][1]);
                atomicAdd(p + 8 * Ndim,     acc[mi][ni][2]);
                atomicAdd(p + 8 * Ndim + 1, acc[mi][ni][3]);
            } else {
                p[0]            = acc[mi][ni][0];
                p[1]            = acc[mi][ni][1];
                p[8 * Ndim]     = acc[mi][ni][2];
                p[8 * Ndim + 1] = acc[mi][ni][3];
            }
        }
    }
}

// ---------------------------------------------------------------------------
__global__ void zero_kernel(float* p, int n) {
    int i = blockIdx.x * blockDim.x + threadIdx.x;
    if (i < n) p[i] = 0.f;
}

// diag_out[b][i] = sum_k W[k][i] * Y[b][k][i]
__global__ void diag_kernel(const float* __restrict__ W,
                            const float* __restrict__ Y,
                            float* __restrict__ dout) {
    int b = blockIdx.x;
    int i = threadIdx.x;   // 256
    const float* Yb = Y + (long)b * CDIM * CDIM;
    float acc = 0.f;
    for (int k = 0; k < CDIM; k++) acc += W[k * CDIM + i] * Yb[k * CDIM + i];
    dout[b * CDIM + i] = acc;
}

// Per (b,h): logits = M_block / (||q||*||k||*sqrt(hw)); softmax over e.
__global__ void attn_kernel(const float* __restrict__ Mg,
                            const float* __restrict__ dq,
                            const float* __restrict__ dk,
                            float* __restrict__ attn) {
    int bh = blockIdx.x;          // 0..31
    int b = bh >> 3, h = bh & 7;
    int warp = threadIdx.x >> 5, lane = threadIdx.x & 31;
    const float inv = 1.0f / 128.0f;   // 1/sqrt(16384)
    int e = lane;
    float nk = rsqrtf(dk[b * CDIM + h * 32 + e]);
    for (int r = 0; r < 4; r++) {
        int c = warp * 4 + r;
        float nq = rsqrtf(dq[b * CDIM + h * 32 + c]);
        float logit = Mg[(long)b * CDIM * CDIM + (h * 32 + c) * CDIM + (h * 32 + e)]
                      * nq * nk * inv;
        float mx = logit;
        for (int o = 16; o; o >>= 1) mx = fmaxf(mx, __shfl_xor_sync(0xffffffffu, mx, o));
        float p = __expf(logit - mx);
        float s = p;
        for (int o = 16; o; o >>= 1) s += __shfl_xor_sync(0xffffffffu, s, o);
        attn[(bh * 32 + c) * 32 + e] = p / s;
    }
}

// Wmix[b][h*32+e][n] = sum_c attn[b][h][c][e] * Wout[h*32+c][n]
__global__ void wmix_kernel(const float* __restrict__ attn,
                            const float* __restrict__ Wout,
                            float* __restrict__ Wmix) {
    int bh = blockIdx.x;
    int b = bh >> 3, h = bh & 7;
    __shared__ float a_s[32 * 32];
    for (int i = threadIdx.x; i < 1024; i += 256) a_s[i] = attn[bh * 1024 + i];
    __syncthreads();
    for (int idx = threadIdx.x; idx < 32 * 256; idx += 256) {
        int e = idx >> 8, n = idx & 255;
        float acc = 0.f;
#pragma unroll
        for (int c2 = 0; c2 < 32; c2++)
            acc += a_s[c2 * 32 + e] * Wout[(h * 32 + c2) * CDIM + n];
        Wmix[(long)b * CDIM * CDIM + (h * 32 + e) * CDIM + n] = acc;
    }
}

// ---------------------------------------------------------------------------
extern "C" void kernel_launch(void* const* d_in, const int* in_sizes, int n_in,
                              void* d_out, int out_size) {
    (void)in_sizes; (void)n_in; (void)out_size;
    const float* x    = (const float*)d_in[0];
    const float* Wq   = (const float*)d_in[1];
    const float* Wk   = (const float*)d_in[2];
    const float* Wv   = (const float*)d_in[3];
    const float* Wout = (const float*)d_in[4];
    float* out = (float*)d_out;

    float *G, *Yq, *Yk, *Mm, *dq, *dk, *attn, *Wmix, *Weff;
    cudaGetSymbolAddress((void**)&G,    g_G);
    cudaGetSymbolAddress((void**)&Yq,   g_Yq);
    cudaGetSymbolAddress((void**)&Yk,   g_Yk);
    cudaGetSymbolAddress((void**)&Mm,   g_Mm);
    cudaGetSymbolAddress((void**)&dq,   g_dq);
    cudaGetSymbolAddress((void**)&dk,   g_dk);
    cudaGetSymbolAddress((void**)&attn, g_attn);
    cudaGetSymbolAddress((void**)&Wmix, g_Wmix);
    cudaGetSymbolAddress((void**)&Weff, g_Weff);

    const long sX = (long)HW * CDIM;     // per-batch x stride
    const long sM = (long)CDIM * CDIM;   // per-batch 256x256 stride

    // G[b] = X_b^T X_b  (split-K: 16 chunks of 1024, atomic accumulate)
    zero_kernel<<<(BATCH * CDIM * CDIM + 255) / 256, 256>>>(G, BATCH * CDIM * CDIM);
    {
        dim3 gr(2 * 2 * 16, 1, BATCH);
        gemm_tf32<true, true><<<gr, 256>>>(x, x, G, CDIM, CDIM, HW, sX, sX, sM, 1024);
    }
    // Yq = G @ Wq ; Yk = G @ Wk
    {
        dim3 gr(4, 1, BATCH);
        gemm_tf32<false, false><<<gr, 256>>>(G, Wq, Yq, CDIM, CDIM, CDIM, sM, 0, sM, CDIM);
        gemm_tf32<false, false><<<gr, 256>>>(G, Wk, Yk, CDIM, CDIM, CDIM, sM, 0, sM, CDIM);
        // Mm = Wq^T @ Yk
        gemm_tf32<true, false><<<gr, 256>>>(Wq, Yk, Mm, CDIM, CDIM, CDIM, 0, sM, sM, CDIM);
    }
    diag_kernel<<<BATCH, 256>>>(Wq, Yq, dq);
    diag_kernel<<<BATCH, 256>>>(Wk, Yk, dk);
    attn_kernel<<<BATCH * HEADS, 256>>>(Mm, dq, dk, attn);
    wmix_kernel<<<BATCH * HEADS, 256>>>(attn, Wout, Wmix);
    // Weff = Wv @ Wmix
    {
        dim3 gr(4, 1, BATCH);
        gemm_tf32<false, false><<<gr, 256>>>(Wv, Wmix, Weff, CDIM, CDIM, CDIM, 0, sM, sM, CDIM);
    }
    // out = X @ Weff
    {
        dim3 gr(128 * 2, 1, BATCH);
        gemm_tf32<false, false><<<gr, 256>>>(x, Weff, out, HW, CDIM, CDIM, sX, sM, sX, CDIM);
    }
}

// round 4
// speedup vs baseline: 1.3627x; 1.3627x over previous
#include <cuda_runtime.h>
#include <cstdint>

#define BATCH 4
#define HW    16384
#define CDIM  256
#define HEADS 8

// Scratch (device globals; no allocations allowed)
__device__ float g_G[BATCH * CDIM * CDIM];     // Gram per batch
__device__ float g_Weff[BATCH * CDIM * CDIM];  // effective per-batch weight

__device__ __forceinline__ uint32_t f2tf(float x) {
    uint32_t r;
    asm("cvt.rna.tf32.f32 %0, %1;" : "=r"(r) : "f"(x));
    return r;
}

__device__ __forceinline__ void mma8(float* c, const uint32_t* a, const uint32_t* b) {
    asm volatile(
        "mma.sync.aligned.m16n8k8.row.col.f32.tf32.tf32.f32 "
        "{%0,%1,%2,%3}, {%4,%5,%6,%7}, {%8,%9}, {%0,%1,%2,%3};"
        : "+f"(c[0]), "+f"(c[1]), "+f"(c[2]), "+f"(c[3])
        : "r"(a[0]), "r"(a[1]), "r"(a[2]), "r"(a[3]), "r"(b[0]), "r"(b[1]));
}

__device__ __forceinline__ void cp16(uint32_t s, const float* g) {
    asm volatile("cp.async.cg.shared.global [%0], [%1], 16;" :: "r"(s), "l"(g));
}

// ---------------------------------------------------------------------------
// Double-buffered tf32 GEMM (cp.async), 128x128 CTA tile, 256 threads.
//  TA=true :  C[m][n] = sum_k A[k][m] * B[k][n]
//  TA=false:  C[m][n] = sum_k A[m][k] * B[k][n]
//  ATOMIC  :  atomicAdd epilogue (split-K).
// fp32 lands raw in smem; cvt.rna.tf32 applied at fragment load (accuracy
// identical to convert-at-store).
// ---------------------------------------------------------------------------
template <bool TA, bool ATOMIC>
__global__ __launch_bounds__(256) void gemm_db(
    const float* __restrict__ Ag, const float* __restrict__ Bg,
    float* __restrict__ Cg, int Mdim, int Ndim, int Kdim,
    long sA, long sB, long sC, int kChunk)
{
    constexpr int AW = TA ? 4352 : 4608;   // words per A buffer
    constexpr int BW = 4352;
    extern __shared__ float smem[];
    float* As = smem;                       // 2 buffers
    float* Bs = smem + 2 * AW;

    const int tilesN = Ndim >> 7;
    const int tilesM = Mdim >> 7;
    const int tileCount = tilesM * tilesN;
    const int tileId = blockIdx.x % tileCount;
    const int split  = blockIdx.x / tileCount;
    const int tm = tileId / tilesN;
    const int tn = tileId % tilesN;

    const float* A  = Ag + (long)blockIdx.z * sA;
    const float* Bp = Bg + (long)blockIdx.z * sB;
    float* Cp = Cg + (long)blockIdx.z * sC;

    const int k0 = split * kChunk;

    const int tid  = threadIdx.x;
    const int lane = tid & 31;
    const int warp = tid >> 5;
    const int wm = warp >> 2;
    const int wn = warp & 3;
    const int g  = lane >> 2;
    const int t4 = lane & 3;

    // per-thread async-copy setup
    const float* gA[4]; uint32_t sAoff[4]; long stepA;
    const float* gB[4]; uint32_t sBoff[4];
#pragma unroll
    for (int r = 0; r < 4; r++) {
        int id = tid + r * 256;
        if (TA) {
            int k = id >> 5, m4 = (id & 31) << 2;
            gA[r] = A + (long)(k0 + k) * Mdim + (tm << 7) + m4;
            sAoff[r] = k * 136 + m4;
        } else {
            int m = id >> 3, k4 = (id & 7) << 2;
            gA[r] = A + (long)((tm << 7) + m) * Kdim + k0 + k4;
            sAoff[r] = m * 36 + k4;
        }
        int k = id >> 5, n4 = (id & 31) << 2;
        gB[r] = Bp + (long)(k0 + k) * Ndim + (tn << 7) + n4;
        sBoff[r] = k * 136 + n4;
    }
    stepA = TA ? (long)32 * Mdim : 32L;
    const long stepB = (long)32 * Ndim;

    const uint32_t sAb = (uint32_t)__cvta_generic_to_shared(As);
    const uint32_t sBb = (uint32_t)__cvta_generic_to_shared(Bs);

    auto issue = [&](int buf) {
#pragma unroll
        for (int r = 0; r < 4; r++) { cp16(sAb + (buf * AW + sAoff[r]) * 4, gA[r]); gA[r] += stepA; }
#pragma unroll
        for (int r = 0; r < 4; r++) { cp16(sBb + (buf * BW + sBoff[r]) * 4, gB[r]); gB[r] += stepB; }
        asm volatile("cp.async.commit_group;");
    };

    float acc[4][4][4];
#pragma unroll
    for (int i = 0; i < 4; i++)
#pragma unroll
        for (int j = 0; j < 4; j++)
#pragma unroll
            for (int r = 0; r < 4; r++) acc[i][j][r] = 0.f;

    const int T = kChunk >> 5;
    issue(0);
    for (int t = 0; t < T; t++) {
        if (t + 1 < T) {
            issue((t + 1) & 1);
            asm volatile("cp.async.wait_group 1;");
        } else {
            asm volatile("cp.async.wait_group 0;");
        }
        __syncthreads();
        const float* Ab = As + (t & 1) * AW;
        const float* Bb = Bs + (t & 1) * BW;
#pragma unroll
        for (int ks = 0; ks < 32; ks += 8) {
            uint32_t af[4][4], bf[4][2];
#pragma unroll
            for (int mi = 0; mi < 4; mi++) {
                int m0 = wm * 64 + mi * 16;
                if (TA) {
                    af[mi][0] = f2tf(Ab[(ks + t4) * 136 + m0 + g]);
                    af[mi][1] = f2tf(Ab[(ks + t4) * 136 + m0 + g + 8]);
                    af[mi][2] = f2tf(Ab[(ks + t4 + 4) * 136 + m0 + g]);
                    af[mi][3] = f2tf(Ab[(ks + t4 + 4) * 136 + m0 + g + 8]);
                } else {
                    af[mi][0] = f2tf(Ab[(m0 + g) * 36 + ks + t4]);
                    af[mi][1] = f2tf(Ab[(m0 + g + 8) * 36 + ks + t4]);
                    af[mi][2] = f2tf(Ab[(m0 + g) * 36 + ks + t4 + 4]);
                    af[mi][3] = f2tf(Ab[(m0 + g + 8) * 36 + ks + t4 + 4]);
                }
            }
#pragma unroll
            for (int ni = 0; ni < 4; ni++) {
                int n0 = wn * 32 + ni * 8;
                bf[ni][0] = f2tf(Bb[(ks + t4) * 136 + n0 + g]);
                bf[ni][1] = f2tf(Bb[(ks + t4 + 4) * 136 + n0 + g]);
            }
#pragma unroll
            for (int mi = 0; mi < 4; mi++)
#pragma unroll
                for (int ni = 0; ni < 4; ni++)
                    mma8(acc[mi][ni], af[mi], bf[ni]);
        }
        __syncthreads();
    }

#pragma unroll
    for (int mi = 0; mi < 4; mi++) {
#pragma unroll
        for (int ni = 0; ni < 4; ni++) {
            int row = (tm << 7) + wm * 64 + mi * 16 + g;
            int col = (tn << 7) + wn * 32 + ni * 8 + t4 * 2;
            float* p = Cp + (long)row * Ndim + col;
            if (ATOMIC) {
                atomicAdd(p,                acc[mi][ni][0]);
                atomicAdd(p + 1,            acc[mi][ni][1]);
                atomicAdd(p + 8 * Ndim,     acc[mi][ni][2]);
                atomicAdd(p + 8 * Ndim + 1, acc[mi][ni][3]);
            } else {
                p[0]            = acc[mi][ni][0];
                p[1]            = acc[mi][ni][1];
                p[8 * Ndim]     = acc[mi][ni][2];
                p[8 * Ndim + 1] = acc[mi][ni][3];
            }
        }
    }
}

// ---------------------------------------------------------------------------
// Fused middle kernel: one CTA per (head, batch). 5 phases:
//  1) [Qh|Kh] = G @ [Wq_h|Wk_h]             (tf32 mma, 256x64)
//  2) Mm = Wq_h^T Kh, dq/dk diagonals       (fp32 fma)
//  3) softmax over e                        (warp shuffles)
//  4) Wmix_h = attn^T @ Wout_h              (fp32 fma)
//  5) Weff += Wv_h @ Wmix_h                 (tf32 mma + atomicAdd)
// smem layout (words):
//  SW   @ 0      : 256*72 = 18432  (tf32 [Wq|Wk], k-major; reused ph4+: SWv 256*36, SWx 32*264)
//  SG   @ 18432  : 64*260 = 16640  (tf32 G m-block, m-major)
//  SQK  @ 35072  : 256*72 = 18432  (fp32 [Qh|Kh], m-major)
//  small@ 53504  : Mm 32*33, attn 32*33, dq 32, dk 32
// total 55680 words = 222720 B
// ---------------------------------------------------------------------------
__global__ __launch_bounds__(256) void fused_middle(
    const float* __restrict__ Gg, const float* __restrict__ Wq,
    const float* __restrict__ Wk, const float* __restrict__ Wv,
    const float* __restrict__ Wout, float* __restrict__ Weff)
{
    extern __shared__ uint32_t smw[];
    uint32_t* SW  = smw;
    uint32_t* SG  = smw + 18432;
    uint32_t* SQK = smw + 35072;
    float* SMM  = (float*)(smw + 53504);
    float* SATT = (float*)(smw + 54560);
    float* SDQ  = (float*)(smw + 55616);
    float* SDK  = (float*)(smw + 55648);

    const int h = blockIdx.x;
    const int b = blockIdx.z;
    const float* G = Gg + (long)b * CDIM * CDIM;
    float* Wf = Weff + (long)b * CDIM * CDIM;

    const int tid  = threadIdx.x;
    const int lane = tid & 31;
    const int warp = tid >> 5;
    const int g  = lane >> 2;
    const int t4 = lane & 3;

    // ---- phase 0: load [Wq_h | Wk_h] as tf32, k-major, stride 72 ----
    for (int i = tid; i < 256 * 64; i += 256) {
        int k = i >> 6, n = i & 63;
        float v = (n < 32) ? Wq[k * CDIM + h * 32 + n]
                           : Wk[k * CDIM + h * 32 + (n - 32)];
        SW[k * 72 + n] = f2tf(v);
    }
    __syncthreads();

    // ---- phase 1: [Qh|Kh] = G @ [Wq_h|Wk_h] ----
    const int m0 = (warp & 3) * 16;       // m within 64-row block
    const int n0 = (warp >> 2) * 32;      // n within 64
    for (int mb = 0; mb < 4; mb++) {
        for (int i = tid; i < 4096; i += 256) {
            int row = i >> 6, c4 = (i & 63) << 2;
            float4 v = *(const float4*)(G + (long)(mb * 64 + row) * 256 + c4);
            uint32_t* d = SG + row * 260 + c4;
            d[0] = f2tf(v.x); d[1] = f2tf(v.y); d[2] = f2tf(v.z); d[3] = f2tf(v.w);
        }
        __syncthreads();
        float acc[4][4];
#pragma unroll
        for (int i = 0; i < 4; i++)
#pragma unroll
            for (int r = 0; r < 4; r++) acc[i][r] = 0.f;
#pragma unroll 8
        for (int ks = 0; ks < 256; ks += 8) {
            uint32_t af[4], bf[4][2];
            af[0] = SG[(m0 + g) * 260 + ks + t4];
            af[1] = SG[(m0 + g + 8) * 260 + ks + t4];
            af[2] = SG[(m0 + g) * 260 + ks + t4 + 4];
            af[3] = SG[(m0 + g + 8) * 260 + ks + t4 + 4];
#pragma unroll
            for (int nf = 0; nf < 4; nf++) {
                int nn = n0 + nf * 8;
                bf[nf][0] = SW[(ks + t4) * 72 + nn + g];
                bf[nf][1] = SW[(ks + t4 + 4) * 72 + nn + g];
            }
#pragma unroll
            for (int nf = 0; nf < 4; nf++) mma8(acc[nf], af, bf[nf]);
        }
#pragma unroll
        for (int nf = 0; nf < 4; nf++) {
            int nn = n0 + nf * 8 + t4 * 2;
            int rr = mb * 64 + m0 + g;
            SQK[rr * 72 + nn]       = __float_as_uint(acc[nf][0]);
            SQK[rr * 72 + nn + 1]   = __float_as_uint(acc[nf][1]);
            SQK[(rr + 8) * 72 + nn]     = __float_as_uint(acc[nf][2]);
            SQK[(rr + 8) * 72 + nn + 1] = __float_as_uint(acc[nf][3]);
        }
        __syncthreads();
    }

    // ---- phase 2: Mm = Wq_h^T Kh, diagonals ----
    {
        int e = tid & 31, cb = warp * 4;
        float a0 = 0.f, a1 = 0.f, a2 = 0.f, a3 = 0.f;
        for (int m = 0; m < 256; m++) {
            float kv = __uint_as_float(SQK[m * 72 + 32 + e]);
            a0 += __uint_as_float(SW[m * 72 + cb + 0]) * kv;
            a1 += __uint_as_float(SW[m * 72 + cb + 1]) * kv;
            a2 += __uint_as_float(SW[m * 72 + cb + 2]) * kv;
            a3 += __uint_as_float(SW[m * 72 + cb + 3]) * kv;
        }
        SMM[(cb + 0) * 33 + e] = a0;
        SMM[(cb + 1) * 33 + e] = a1;
        SMM[(cb + 2) * 33 + e] = a2;
        SMM[(cb + 3) * 33 + e] = a3;
        if (tid < 32) {
            float d = 0.f;
            for (int m = 0; m < 256; m++)
                d += __uint_as_float(SW[m * 72 + tid]) * __uint_as_float(SQK[m * 72 + tid]);
            SDQ[tid] = d;
        } else if (tid < 64) {
            int e2 = tid - 32;
            float d = 0.f;
            for (int m = 0; m < 256; m++)
                d += __uint_as_float(SW[m * 72 + 32 + e2]) * __uint_as_float(SQK[m * 72 + 32 + e2]);
            SDK[e2] = d;
        }
    }
    __syncthreads();

    // ---- phase 3: softmax over e ----
    {
        float nk = rsqrtf(SDK[lane]);
#pragma unroll
        for (int r = 0; r < 4; r++) {
            int c = warp * 4 + r;
            float nq = rsqrtf(SDQ[c]);
            float l = SMM[c * 33 + lane] * nq * nk * (1.0f / 128.0f);
            float mx = l;
            for (int o = 16; o; o >>= 1) mx = fmaxf(mx, __shfl_xor_sync(0xffffffffu, mx, o));
            float p = __expf(l - mx);
            float s = p;
            for (int o = 16; o; o >>= 1) s += __shfl_xor_sync(0xffffffffu, s, o);
            SATT[c * 33 + lane] = p / s;
        }
    }
    __syncthreads();

    // ---- phase 4: sWv (A-operand) + sWmix (B-operand), overwrites SW region ----
    uint32_t* SWv = smw;          // 256*36 = 9216 words
    uint32_t* SWx = smw + 9216;   // 32*264 = 8448 words
    {
        float wo[32];
#pragma unroll
        for (int c = 0; c < 32; c++) wo[c] = Wout[(h * 32 + c) * CDIM + tid];
        for (int e = 0; e < 32; e++) {
            float a = 0.f;
#pragma unroll
            for (int c = 0; c < 32; c++) a += SATT[c * 33 + e] * wo[c];
            SWx[e * 264 + tid] = f2tf(a);
        }
        for (int i = tid; i < 8192; i += 256) {
            int m = i >> 5, e = i & 31;
            SWv[m * 36 + e] = f2tf(Wv[m * CDIM + h * 32 + e]);
        }
    }
    __syncthreads();

    // ---- phase 5: Weff += Wv_h @ Wmix_h (256x256, K=32) ----
    {
        const int m0w = warp * 32;
        for (int nc = 0; nc < 4; nc++) {
            float acc[2][8][4];
#pragma unroll
            for (int mi = 0; mi < 2; mi++)
#pragma unroll
                for (int nf = 0; nf < 8; nf++)
#pragma unroll
                    for (int r = 0; r < 4; r++) acc[mi][nf][r] = 0.f;
#pragma unroll
            for (int ks = 0; ks < 32; ks += 8) {
                uint32_t af[2][4];
#pragma unroll
                for (int mi = 0; mi < 2; mi++) {
                    int mm = m0w + mi * 16;
                    af[mi][0] = SWv[(mm + g) * 36 + ks + t4];
                    af[mi][1] = SWv[(mm + g + 8) * 36 + ks + t4];
                    af[mi][2] = SWv[(mm + g) * 36 + ks + t4 + 4];
                    af[mi][3] = SWv[(mm + g + 8) * 36 + ks + t4 + 4];
                }
#pragma unroll
                for (int nf = 0; nf < 8; nf++) {
                    int nn = nc * 64 + nf * 8 + g;
                    uint32_t bf[2];
                    bf[0] = SWx[(ks + t4) * 264 + nn];
                    bf[1] = SWx[(ks + t4 + 4) * 264 + nn];
                    mma8(acc[0][nf], af[0], bf);
                    mma8(acc[1][nf], af[1], bf);
                }
            }
#pragma unroll
            for (int mi = 0; mi < 2; mi++) {
#pragma unroll
                for (int nf = 0; nf < 8; nf++) {
                    int rr = m0w + mi * 16 + g;
                    int cc = nc * 64 + nf * 8 + t4 * 2;
                    atomicAdd(&Wf[rr * 256 + cc],           acc[mi][nf][0]);
                    atomicAdd(&Wf[rr * 256 + cc + 1],       acc[mi][nf][1]);
                    atomicAdd(&Wf[(rr + 8) * 256 + cc],     acc[mi][nf][2]);
                    atomicAdd(&Wf[(rr + 8) * 256 + cc + 1], acc[mi][nf][3]);
                }
            }
        }
    }
}

// ---------------------------------------------------------------------------
__global__ void zero2_kernel(float* a, float* b, int n) {
    int i = blockIdx.x * blockDim.x + threadIdx.x;
    if (i < n) { a[i] = 0.f; b[i] = 0.f; }
}

// ---------------------------------------------------------------------------
extern "C" void kernel_launch(void* const* d_in, const int* in_sizes, int n_in,
                              void* d_out, int out_size) {
    (void)in_sizes; (void)n_in; (void)out_size;
    const float* x    = (const float*)d_in[0];
    const float* Wq   = (const float*)d_in[1];
    const float* Wk   = (const float*)d_in[2];
    const float* Wv   = (const float*)d_in[3];
    const float* Wout = (const float*)d_in[4];
    float* out = (float*)d_out;

    float *G, *Weff;
    cudaGetSymbolAddress((void**)&G,    g_G);
    cudaGetSymbolAddress((void**)&Weff, g_Weff);

    const long sX = (long)HW * CDIM;
    const long sM = (long)CDIM * CDIM;

    const int smemGram  = (2 * 4352 + 2 * 4352) * 4;   // 69632
    const int smemOut   = (2 * 4608 + 2 * 4352) * 4;   // 71680
    const int smemFused = 55680 * 4;                    // 222720

    cudaFuncSetAttribute(gemm_db<true, true>,
                         cudaFuncAttributeMaxDynamicSharedMemorySize, smemGram);
    cudaFuncSetAttribute(gemm_db<false, false>,
                         cudaFuncAttributeMaxDynamicSharedMemorySize, smemOut);
    cudaFuncSetAttribute(fused_middle,
                         cudaFuncAttributeMaxDynamicSharedMemorySize, smemFused);

    // zero G and Weff
    zero2_kernel<<<(BATCH * CDIM * CDIM + 255) / 256, 256>>>(G, Weff, BATCH * CDIM * CDIM);

    // G[b] = X_b^T X_b  (split-K 16, atomic)
    {
        dim3 gr(4 * 16, 1, BATCH);
        gemm_db<true, true><<<gr, 256, smemGram>>>(x, x, G, CDIM, CDIM, HW, sX, sX, sM, 1024);
    }

    // fused middle: everything between the two big GEMMs
    {
        dim3 gr(HEADS, 1, BATCH);
        fused_middle<<<gr, 256, smemFused>>>(G, Wq, Wk, Wv, Wout, Weff);
    }

    // out = X @ Weff
    {
        dim3 gr(128 * 2, 1, BATCH);
        gemm_db<false, false><<<gr, 256, smemOut>>>(x, Weff, out, HW, CDIM, CDIM, sX, sM, sX, CDIM);
    }
}

// round 5
// speedup vs baseline: 1.4600x; 1.0714x over previous
#include <cuda_runtime.h>
#include <cstdint>

#define BATCH 4
#define HW    16384
#define CDIM  256
#define HEADS 8

__device__ float g_G[BATCH * CDIM * CDIM];
__device__ float g_Weff[BATCH * CDIM * CDIM];

__device__ __forceinline__ uint32_t f2tf(float x) {
    uint32_t r;
    asm("cvt.rna.tf32.f32 %0, %1;" : "=r"(r) : "f"(x));
    return r;
}

__device__ __forceinline__ void mma8(float* c, const uint32_t* a, const uint32_t* b) {
    asm volatile(
        "mma.sync.aligned.m16n8k8.row.col.f32.tf32.tf32.f32 "
        "{%0,%1,%2,%3}, {%4,%5,%6,%7}, {%8,%9}, {%0,%1,%2,%3};"
        : "+f"(c[0]), "+f"(c[1]), "+f"(c[2]), "+f"(c[3])
        : "r"(a[0]), "r"(a[1]), "r"(a[2]), "r"(a[3]), "r"(b[0]), "r"(b[1]));
}

__device__ __forceinline__ void cp16(uint32_t s, const float* g) {
    asm volatile("cp.async.cg.shared.global [%0], [%1], 16;" :: "r"(s), "l"(g));
}

// ---------------------------------------------------------------------------
// 3-stage cp.async tf32 GEMM, 128x128 CTA tile, 256 threads, 2 CTAs/SM.
//  TA=true :  C[m][n] = sum_k A[k][m] * B[k][n]
//  TA=false:  C[m][n] = sum_k A[m][k] * B[k][n]
//  ATOMIC  :  atomicAdd epilogue (split-K)
//  SYM     :  C symmetric 256x256 (Gram): compute tiles (0,0),(0,1),(1,1),
//             mirror the off-diagonal tile in the epilogue.
// ---------------------------------------------------------------------------
template <bool TA, bool ATOMIC, bool SYM>
__global__ __launch_bounds__(256, 2) void gemm_db(
    const float* __restrict__ Ag, const float* __restrict__ Bg,
    float* __restrict__ Cg, int Mdim, int Ndim, int Kdim,
    long sA, long sB, long sC, int kChunk)
{
    constexpr int AW = TA ? 4352 : 4608;
    constexpr int BW = 4352;
    extern __shared__ float smem[];
    float* As = smem;                 // 3 buffers
    float* Bs = smem + 3 * AW;

    int tm, tn, split;
    if (SYM) {
        const int tileId = blockIdx.x % 3;
        split = blockIdx.x / 3;
        tm = (tileId == 2) ? 1 : 0;
        tn = (tileId == 0) ? 0 : 1;
    } else {
        const int tilesN = Ndim >> 7;
        const int tilesM = Mdim >> 7;
        const int tileCount = tilesM * tilesN;
        const int tileId = blockIdx.x % tileCount;
        split = blockIdx.x / tileCount;
        tm = tileId / tilesN;
        tn = tileId % tilesN;
    }

    const float* A  = Ag + (long)blockIdx.z * sA;
    const float* Bp = Bg + (long)blockIdx.z * sB;
    float* Cp = Cg + (long)blockIdx.z * sC;

    const int k0 = split * kChunk;

    const int tid  = threadIdx.x;
    const int lane = tid & 31;
    const int warp = tid >> 5;
    const int wm = warp >> 2;
    const int wn = warp & 3;
    const int g  = lane >> 2;
    const int t4 = lane & 3;

    const float* gA[4]; uint32_t sAoff[4];
    const float* gB[4]; uint32_t sBoff[4];
#pragma unroll
    for (int r = 0; r < 4; r++) {
        int id = tid + r * 256;
        if (TA) {
            int k = id >> 5, m4 = (id & 31) << 2;
            gA[r] = A + (long)(k0 + k) * Mdim + (tm << 7) + m4;
            sAoff[r] = k * 136 + m4;
        } else {
            int m = id >> 3, k4 = (id & 7) << 2;
            gA[r] = A + (long)((tm << 7) + m) * Kdim + k0 + k4;
            sAoff[r] = m * 36 + k4;
        }
        int k = id >> 5, n4 = (id & 31) << 2;
        gB[r] = Bp + (long)(k0 + k) * Ndim + (tn << 7) + n4;
        sBoff[r] = k * 136 + n4;
    }
    const long stepA = TA ? (long)32 * Mdim : 32L;
    const long stepB = (long)32 * Ndim;

    const uint32_t sAb = (uint32_t)__cvta_generic_to_shared(As);
    const uint32_t sBb = (uint32_t)__cvta_generic_to_shared(Bs);

    auto issue = [&](int buf) {
#pragma unroll
        for (int r = 0; r < 4; r++) { cp16(sAb + (buf * AW + sAoff[r]) * 4, gA[r]); gA[r] += stepA; }
#pragma unroll
        for (int r = 0; r < 4; r++) { cp16(sBb + (buf * BW + sBoff[r]) * 4, gB[r]); gB[r] += stepB; }
        asm volatile("cp.async.commit_group;");
    };

    float acc[4][4][4];
#pragma unroll
    for (int i = 0; i < 4; i++)
#pragma unroll
        for (int j = 0; j < 4; j++)
#pragma unroll
            for (int r = 0; r < 4; r++) acc[i][j][r] = 0.f;

    const int T = kChunk >> 5;
    issue(0);
    if (T > 1) issue(1);
    int buf = 0;
    for (int t = 0; t < T; t++) {
        if (t + 2 < T) {
            issue((buf + 2) % 3);
            asm volatile("cp.async.wait_group 2;");
        } else if (t + 1 < T) {
            asm volatile("cp.async.wait_group 1;");
        } else {
            asm volatile("cp.async.wait_group 0;");
        }
        __syncthreads();
        const float* Ab = As + buf * AW;
        const float* Bb = Bs + buf * BW;
#pragma unroll
        for (int ks = 0; ks < 32; ks += 8) {
            uint32_t af[4][4], bf[4][2];
#pragma unroll
            for (int mi = 0; mi < 4; mi++) {
                int m0 = wm * 64 + mi * 16;
                if (TA) {
                    af[mi][0] = f2tf(Ab[(ks + t4) * 136 + m0 + g]);
                    af[mi][1] = f2tf(Ab[(ks + t4) * 136 + m0 + g + 8]);
                    af[mi][2] = f2tf(Ab[(ks + t4 + 4) * 136 + m0 + g]);
                    af[mi][3] = f2tf(Ab[(ks + t4 + 4) * 136 + m0 + g + 8]);
                } else {
                    af[mi][0] = f2tf(Ab[(m0 + g) * 36 + ks + t4]);
                    af[mi][1] = f2tf(Ab[(m0 + g + 8) * 36 + ks + t4]);
                    af[mi][2] = f2tf(Ab[(m0 + g) * 36 + ks + t4 + 4]);
                    af[mi][3] = f2tf(Ab[(m0 + g + 8) * 36 + ks + t4 + 4]);
                }
            }
#pragma unroll
            for (int ni = 0; ni < 4; ni++) {
                int n0 = wn * 32 + ni * 8;
                bf[ni][0] = f2tf(Bb[(ks + t4) * 136 + n0 + g]);
                bf[ni][1] = f2tf(Bb[(ks + t4 + 4) * 136 + n0 + g]);
            }
#pragma unroll
            for (int mi = 0; mi < 4; mi++)
#pragma unroll
                for (int ni = 0; ni < 4; ni++)
                    mma8(acc[mi][ni], af[mi], bf[ni]);
        }
        __syncthreads();
        buf = (buf + 1) % 3;
    }

    const bool mirror = SYM && (tm != tn);
#pragma unroll
    for (int mi = 0; mi < 4; mi++) {
#pragma unroll
        for (int ni = 0; ni < 4; ni++) {
            int row = (tm << 7) + wm * 64 + mi * 16 + g;
            int col = (tn << 7) + wn * 32 + ni * 8 + t4 * 2;
            float* p = Cp + (long)row * Ndim + col;
            if (ATOMIC) {
                atomicAdd(p,                acc[mi][ni][0]);
                atomicAdd(p + 1,            acc[mi][ni][1]);
                atomicAdd(p + 8 * Ndim,     acc[mi][ni][2]);
                atomicAdd(p + 8 * Ndim + 1, acc[mi][ni][3]);
                if (mirror) {
                    atomicAdd(Cp + (long)col * Ndim + row,             acc[mi][ni][0]);
                    atomicAdd(Cp + (long)(col + 1) * Ndim + row,       acc[mi][ni][1]);
                    atomicAdd(Cp + (long)col * Ndim + row + 8,         acc[mi][ni][2]);
                    atomicAdd(Cp + (long)(col + 1) * Ndim + row + 8,   acc[mi][ni][3]);
                }
            } else {
                p[0]            = acc[mi][ni][0];
                p[1]            = acc[mi][ni][1];
                p[8 * Ndim]     = acc[mi][ni][2];
                p[8 * Ndim + 1] = acc[mi][ni][3];
            }
        }
    }
}

// ---------------------------------------------------------------------------
// Fused middle kernel (unchanged from R3): one CTA per (head, batch).
// ---------------------------------------------------------------------------
__global__ __launch_bounds__(256) void fused_middle(
    const float* __restrict__ Gg, const float* __restrict__ Wq,
    const float* __restrict__ Wk, const float* __restrict__ Wv,
    const float* __restrict__ Wout, float* __restrict__ Weff)
{
    extern __shared__ uint32_t smw[];
    uint32_t* SW  = smw;
    uint32_t* SG  = smw + 18432;
    uint32_t* SQK = smw + 35072;
    float* SMM  = (float*)(smw + 53504);
    float* SATT = (float*)(smw + 54560);
    float* SDQ  = (float*)(smw + 55616);
    float* SDK  = (float*)(smw + 55648);

    const int h = blockIdx.x;
    const int b = blockIdx.z;
    const float* G = Gg + (long)b * CDIM * CDIM;
    float* Wf = Weff + (long)b * CDIM * CDIM;

    const int tid  = threadIdx.x;
    const int lane = tid & 31;
    const int warp = tid >> 5;
    const int g  = lane >> 2;
    const int t4 = lane & 3;

    for (int i = tid; i < 256 * 64; i += 256) {
        int k = i >> 6, n = i & 63;
        float v = (n < 32) ? Wq[k * CDIM + h * 32 + n]
                           : Wk[k * CDIM + h * 32 + (n - 32)];
        SW[k * 72 + n] = f2tf(v);
    }
    __syncthreads();

    const int m0 = (warp & 3) * 16;
    const int n0 = (warp >> 2) * 32;
    for (int mb = 0; mb < 4; mb++) {
        for (int i = tid; i < 4096; i += 256) {
            int row = i >> 6, c4 = (i & 63) << 2;
            float4 v = *(const float4*)(G + (long)(mb * 64 + row) * 256 + c4);
            uint32_t* d = SG + row * 260 + c4;
            d[0] = f2tf(v.x); d[1] = f2tf(v.y); d[2] = f2tf(v.z); d[3] = f2tf(v.w);
        }
        __syncthreads();
        float acc[4][4];
#pragma unroll
        for (int i = 0; i < 4; i++)
#pragma unroll
            for (int r = 0; r < 4; r++) acc[i][r] = 0.f;
#pragma unroll 8
        for (int ks = 0; ks < 256; ks += 8) {
            uint32_t af[4], bf[4][2];
            af[0] = SG[(m0 + g) * 260 + ks + t4];
            af[1] = SG[(m0 + g + 8) * 260 + ks + t4];
            af[2] = SG[(m0 + g) * 260 + ks + t4 + 4];
            af[3] = SG[(m0 + g + 8) * 260 + ks + t4 + 4];
#pragma unroll
            for (int nf = 0; nf < 4; nf++) {
                int nn = n0 + nf * 8;
                bf[nf][0] = SW[(ks + t4) * 72 + nn + g];
                bf[nf][1] = SW[(ks + t4 + 4) * 72 + nn + g];
            }
#pragma unroll
            for (int nf = 0; nf < 4; nf++) mma8(acc[nf], af, bf[nf]);
        }
#pragma unroll
        for (int nf = 0; nf < 4; nf++) {
            int nn = n0 + nf * 8 + t4 * 2;
            int rr = mb * 64 + m0 + g;
            SQK[rr * 72 + nn]       = __float_as_uint(acc[nf][0]);
            SQK[rr * 72 + nn + 1]   = __float_as_uint(acc[nf][1]);
            SQK[(rr + 8) * 72 + nn]     = __float_as_uint(acc[nf][2]);
            SQK[(rr + 8) * 72 + nn + 1] = __float_as_uint(acc[nf][3]);
        }
        __syncthreads();
    }

    {
        int e = tid & 31, cb = warp * 4;
        float a0 = 0.f, a1 = 0.f, a2 = 0.f, a3 = 0.f;
        for (int m = 0; m < 256; m++) {
            float kv = __uint_as_float(SQK[m * 72 + 32 + e]);
            a0 += __uint_as_float(SW[m * 72 + cb + 0]) * kv;
            a1 += __uint_as_float(SW[m * 72 + cb + 1]) * kv;
            a2 += __uint_as_float(SW[m * 72 + cb + 2]) * kv;
            a3 += __uint_as_float(SW[m * 72 + cb + 3]) * kv;
        }
        SMM[(cb + 0) * 33 + e] = a0;
        SMM[(cb + 1) * 33 + e] = a1;
        SMM[(cb + 2) * 33 + e] = a2;
        SMM[(cb + 3) * 33 + e] = a3;
        if (tid < 32) {
            float d = 0.f;
            for (int m = 0; m < 256; m++)
                d += __uint_as_float(SW[m * 72 + tid]) * __uint_as_float(SQK[m * 72 + tid]);
            SDQ[tid] = d;
        } else if (tid < 64) {
            int e2 = tid - 32;
            float d = 0.f;
            for (int m = 0; m < 256; m++)
                d += __uint_as_float(SW[m * 72 + 32 + e2]) * __uint_as_float(SQK[m * 72 + 32 + e2]);
            SDK[e2] = d;
        }
    }
    __syncthreads();

    {
        float nk = rsqrtf(SDK[lane]);
#pragma unroll
        for (int r = 0; r < 4; r++) {
            int c = warp * 4 + r;
            float nq = rsqrtf(SDQ[c]);
            float l = SMM[c * 33 + lane] * nq * nk * (1.0f / 128.0f);
            float mx = l;
            for (int o = 16; o; o >>= 1) mx = fmaxf(mx, __shfl_xor_sync(0xffffffffu, mx, o));
            float p = __expf(l - mx);
            float s = p;
            for (int o = 16; o; o >>= 1) s += __shfl_xor_sync(0xffffffffu, s, o);
            SATT[c * 33 + lane] = p / s;
        }
    }
    __syncthreads();

    uint32_t* SWv = smw;
    uint32_t* SWx = smw + 9216;
    {
        float wo[32];
#pragma unroll
        for (int c = 0; c < 32; c++) wo[c] = Wout[(h * 32 + c) * CDIM + tid];
        for (int e = 0; e < 32; e++) {
            float a = 0.f;
#pragma unroll
            for (int c = 0; c < 32; c++) a += SATT[c * 33 + e] * wo[c];
            SWx[e * 264 + tid] = f2tf(a);
        }
        for (int i = tid; i < 8192; i += 256) {
            int m = i >> 5, e = i & 31;
            SWv[m * 36 + e] = f2tf(Wv[m * CDIM + h * 32 + e]);
        }
    }
    __syncthreads();

    {
        const int m0w = warp * 32;
        for (int nc = 0; nc < 4; nc++) {
            float acc[2][8][4];
#pragma unroll
            for (int mi = 0; mi < 2; mi++)
#pragma unroll
                for (int nf = 0; nf < 8; nf++)
#pragma unroll
                    for (int r = 0; r < 4; r++) acc[mi][nf][r] = 0.f;
#pragma unroll
            for (int ks = 0; ks < 32; ks += 8) {
                uint32_t af[2][4];
#pragma unroll
                for (int mi = 0; mi < 2; mi++) {
                    int mm = m0w + mi * 16;
                    af[mi][0] = SWv[(mm + g) * 36 + ks + t4];
                    af[mi][1] = SWv[(mm + g + 8) * 36 + ks + t4];
                    af[mi][2] = SWv[(mm + g) * 36 + ks + t4 + 4];
                    af[mi][3] = SWv[(mm + g + 8) * 36 + ks + t4 + 4];
                }
#pragma unroll
                for (int nf = 0; nf < 8; nf++) {
                    int nn = nc * 64 + nf * 8 + g;
                    uint32_t bf[2];
                    bf[0] = SWx[(ks + t4) * 264 + nn];
                    bf[1] = SWx[(ks + t4 + 4) * 264 + nn];
                    mma8(acc[0][nf], af[0], bf);
                    mma8(acc[1][nf], af[1], bf);
                }
            }
#pragma unroll
            for (int mi = 0; mi < 2; mi++) {
#pragma unroll
                for (int nf = 0; nf < 8; nf++) {
                    int rr = m0w + mi * 16 + g;
                    int cc = nc * 64 + nf * 8 + t4 * 2;
                    atomicAdd(&Wf[rr * 256 + cc],           acc[mi][nf][0]);
                    atomicAdd(&Wf[rr * 256 + cc + 1],       acc[mi][nf][1]);
                    atomicAdd(&Wf[(rr + 8) * 256 + cc],     acc[mi][nf][2]);
                    atomicAdd(&Wf[(rr + 8) * 256 + cc + 1], acc[mi][nf][3]);
                }
            }
        }
    }
}

// ---------------------------------------------------------------------------
extern "C" void kernel_launch(void* const* d_in, const int* in_sizes, int n_in,
                              void* d_out, int out_size) {
    (void)in_sizes; (void)n_in; (void)out_size;
    const float* x    = (const float*)d_in[0];
    const float* Wq   = (const float*)d_in[1];
    const float* Wk   = (const float*)d_in[2];
    const float* Wv   = (const float*)d_in[3];
    const float* Wout = (const float*)d_in[4];
    float* out = (float*)d_out;

    float *G, *Weff;
    cudaGetSymbolAddress((void**)&G,    g_G);
    cudaGetSymbolAddress((void**)&Weff, g_Weff);

    const long sX = (long)HW * CDIM;
    const long sM = (long)CDIM * CDIM;

    const int smemGram  = 3 * (4352 + 4352) * 4;   // 104448
    const int smemOut   = 3 * (4608 + 4352) * 4;   // 107520
    const int smemFused = 55680 * 4;               // 222720

    cudaFuncSetAttribute(gemm_db<true, true, true>,
                         cudaFuncAttributeMaxDynamicSharedMemorySize, smemGram);
    cudaFuncSetAttribute(gemm_db<false, false, false>,
                         cudaFuncAttributeMaxDynamicSharedMemorySize, smemOut);
    cudaFuncSetAttribute(fused_middle,
                         cudaFuncAttributeMaxDynamicSharedMemorySize, smemFused);

    cudaMemsetAsync(G,    0, BATCH * CDIM * CDIM * sizeof(float));
    cudaMemsetAsync(Weff, 0, BATCH * CDIM * CDIM * sizeof(float));

    // G[b] = X_b^T X_b  (symmetric: 3 tiles, split-K 16, atomic + mirror)
    {
        dim3 gr(3 * 16, 1, BATCH);
        gemm_db<true, true, true><<<gr, 256, smemGram>>>(x, x, G, CDIM, CDIM, HW, sX, sX, sM, 1024);
    }

    // fused middle
    {
        dim3 gr(HEADS, 1, BATCH);
        fused_middle<<<gr, 256, smemFused>>>(G, Wq, Wk, Wv, Wout, Weff);
    }

    // out = X @ Weff
    {
        dim3 gr(128 * 2, 1, BATCH);
        gemm_db<false, false, false><<<gr, 256, smemOut>>>(x, Weff, out, HW, CDIM, CDIM, sX, sM, sX, CDIM);
    }
}

// round 6
// speedup vs baseline: 1.5580x; 1.0671x over previous
#include <cuda_runtime.h>
#include <cstdint>

#define BATCH 4
#define HW    16384
#define CDIM  256
#define HEADS 8

__device__ float g_G[BATCH * CDIM * CDIM];
__device__ float g_Weff[BATCH * CDIM * CDIM];

__device__ __forceinline__ uint32_t f2tf(float x) {
    uint32_t r;
    asm("cvt.rna.tf32.f32 %0, %1;" : "=r"(r) : "f"(x));
    return r;
}

__device__ __forceinline__ void mma8(float* c, const uint32_t* a, const uint32_t* b) {
    asm volatile(
        "mma.sync.aligned.m16n8k8.row.col.f32.tf32.tf32.f32 "
        "{%0,%1,%2,%3}, {%4,%5,%6,%7}, {%8,%9}, {%0,%1,%2,%3};"
        : "+f"(c[0]), "+f"(c[1]), "+f"(c[2]), "+f"(c[3])
        : "r"(a[0]), "r"(a[1]), "r"(a[2]), "r"(a[3]), "r"(b[0]), "r"(b[1]));
}

__device__ __forceinline__ void cp16(uint32_t s, const float* g) {
    asm volatile("cp.async.cg.shared.global [%0], [%1], 16;" :: "r"(s), "l"(g));
}

// ---------------------------------------------------------------------------
// 3-stage cp.async tf32 GEMM, 128x128 CTA tile, 256 threads, 2 CTAs/SM.
//  TA    :  A is K-major ([k][m]) vs M-major ([m][k])
//  ATOMIC:  atomicAdd epilogue (split-K)
//  SYM   :  C symmetric (Gram): tiles (0,0),(0,1),(1,1); mirror off-diag;
//           diagonal tiles alias B smem to A smem (skip B loads entirely).
//  CVTB  :  apply cvt.rna.tf32 to B fragments (false when B pre-rounded).
// ---------------------------------------------------------------------------
template <bool TA, bool ATOMIC, bool SYM, bool CVTB>
__global__ __launch_bounds__(256, 2) void gemm_db(
    const float* __restrict__ Ag, const float* __restrict__ Bg,
    float* __restrict__ Cg, int Mdim, int Ndim, int Kdim,
    long sA, long sB, long sC, int kChunk)
{
    constexpr int AW = TA ? 4352 : 4608;
    constexpr int BW = 4352;
    extern __shared__ float smem[];
    float* As = smem;                 // 3 buffers
    float* Bs = smem + 3 * AW;

    int tm, tn, split;
    if (SYM) {
        const int tileId = blockIdx.x % 3;
        split = blockIdx.x / 3;
        tm = (tileId == 2) ? 1 : 0;
        tn = (tileId == 0) ? 0 : 1;
    } else {
        const int tilesN = Ndim >> 7;
        const int tilesM = Mdim >> 7;
        const int tileCount = tilesM * tilesN;
        const int tileId = blockIdx.x % tileCount;
        split = blockIdx.x / tileCount;
        tm = tileId / tilesN;
        tn = tileId % tilesN;
    }
    const bool same = SYM && (tm == tn);   // diagonal Gram tile: B == A

    const float* A  = Ag + (long)blockIdx.z * sA;
    const float* Bp = Bg + (long)blockIdx.z * sB;
    float* Cp = Cg + (long)blockIdx.z * sC;

    const int k0 = split * kChunk;

    const int tid  = threadIdx.x;
    const int lane = tid & 31;
    const int warp = tid >> 5;
    const int wm = warp >> 2;
    const int wn = warp & 3;
    const int g  = lane >> 2;
    const int t4 = lane & 3;

    const float* gA[4]; uint32_t sAoff[4];
    const float* gB[4]; uint32_t sBoff[4];
#pragma unroll
    for (int r = 0; r < 4; r++) {
        int id = tid + r * 256;
        if (TA) {
            int k = id >> 5, m4 = (id & 31) << 2;
            gA[r] = A + (long)(k0 + k) * Mdim + (tm << 7) + m4;
            sAoff[r] = k * 136 + m4;
        } else {
            int m = id >> 3, k4 = (id & 7) << 2;
            gA[r] = A + (long)((tm << 7) + m) * Kdim + k0 + k4;
            sAoff[r] = m * 36 + k4;
        }
        int k = id >> 5, n4 = (id & 31) << 2;
        gB[r] = Bp + (long)(k0 + k) * Ndim + (tn << 7) + n4;
        sBoff[r] = k * 136 + n4;
    }
    const long stepA = TA ? (long)32 * Mdim : 32L;
    const long stepB = (long)32 * Ndim;

    const uint32_t sAb = (uint32_t)__cvta_generic_to_shared(As);
    const uint32_t sBb = (uint32_t)__cvta_generic_to_shared(Bs);

    auto issue = [&](int buf) {
#pragma unroll
        for (int r = 0; r < 4; r++) { cp16(sAb + (buf * AW + sAoff[r]) * 4, gA[r]); gA[r] += stepA; }
        if (!same) {
#pragma unroll
            for (int r = 0; r < 4; r++) { cp16(sBb + (buf * BW + sBoff[r]) * 4, gB[r]); gB[r] += stepB; }
        }
        asm volatile("cp.async.commit_group;");
    };

    float acc[4][4][4];
#pragma unroll
    for (int i = 0; i < 4; i++)
#pragma unroll
        for (int j = 0; j < 4; j++)
#pragma unroll
            for (int r = 0; r < 4; r++) acc[i][j][r] = 0.f;

    const int T = kChunk >> 5;
    issue(0);
    if (T > 1) issue(1);
    int buf = 0;
    for (int t = 0; t < T; t++) {
        if (t + 2 < T) {
            issue((buf + 2) % 3);
            asm volatile("cp.async.wait_group 2;");
        } else if (t + 1 < T) {
            asm volatile("cp.async.wait_group 1;");
        } else {
            asm volatile("cp.async.wait_group 0;");
        }
        __syncthreads();
        const float* Ab = As + buf * AW;
        const float* Bb = same ? Ab : (Bs + buf * BW);
#pragma unroll
        for (int ks = 0; ks < 32; ks += 8) {
            uint32_t af[4][4], bf[4][2];
#pragma unroll
            for (int mi = 0; mi < 4; mi++) {
                int m0 = wm * 64 + mi * 16;
                if (TA) {
                    af[mi][0] = f2tf(Ab[(ks + t4) * 136 + m0 + g]);
                    af[mi][1] = f2tf(Ab[(ks + t4) * 136 + m0 + g + 8]);
                    af[mi][2] = f2tf(Ab[(ks + t4 + 4) * 136 + m0 + g]);
                    af[mi][3] = f2tf(Ab[(ks + t4 + 4) * 136 + m0 + g + 8]);
                } else {
                    af[mi][0] = f2tf(Ab[(m0 + g) * 36 + ks + t4]);
                    af[mi][1] = f2tf(Ab[(m0 + g + 8) * 36 + ks + t4]);
                    af[mi][2] = f2tf(Ab[(m0 + g) * 36 + ks + t4 + 4]);
                    af[mi][3] = f2tf(Ab[(m0 + g + 8) * 36 + ks + t4 + 4]);
                }
            }
#pragma unroll
            for (int ni = 0; ni < 4; ni++) {
                int n0 = wn * 32 + ni * 8;
                if (CVTB) {
                    bf[ni][0] = f2tf(Bb[(ks + t4) * 136 + n0 + g]);
                    bf[ni][1] = f2tf(Bb[(ks + t4 + 4) * 136 + n0 + g]);
                } else {
                    bf[ni][0] = __float_as_uint(Bb[(ks + t4) * 136 + n0 + g]);
                    bf[ni][1] = __float_as_uint(Bb[(ks + t4 + 4) * 136 + n0 + g]);
                }
            }
#pragma unroll
            for (int mi = 0; mi < 4; mi++)
#pragma unroll
                for (int ni = 0; ni < 4; ni++)
                    mma8(acc[mi][ni], af[mi], bf[ni]);
        }
        __syncthreads();
        buf = (buf + 1) % 3;
    }

    const bool mirror = SYM && (tm != tn);
#pragma unroll
    for (int mi = 0; mi < 4; mi++) {
#pragma unroll
        for (int ni = 0; ni < 4; ni++) {
            int row = (tm << 7) + wm * 64 + mi * 16 + g;
            int col = (tn << 7) + wn * 32 + ni * 8 + t4 * 2;
            float* p = Cp + (long)row * Ndim + col;
            if (ATOMIC) {
                atomicAdd(p,                acc[mi][ni][0]);
                atomicAdd(p + 1,            acc[mi][ni][1]);
                atomicAdd(p + 8 * Ndim,     acc[mi][ni][2]);
                atomicAdd(p + 8 * Ndim + 1, acc[mi][ni][3]);
                if (mirror) {
                    atomicAdd(Cp + (long)col * Ndim + row,             acc[mi][ni][0]);
                    atomicAdd(Cp + (long)(col + 1) * Ndim + row,       acc[mi][ni][1]);
                    atomicAdd(Cp + (long)col * Ndim + row + 8,         acc[mi][ni][2]);
                    atomicAdd(Cp + (long)(col + 1) * Ndim + row + 8,   acc[mi][ni][3]);
                }
            } else {
                p[0]            = acc[mi][ni][0];
                p[1]            = acc[mi][ni][1];
                p[8 * Ndim]     = acc[mi][ni][2];
                p[8 * Ndim + 1] = acc[mi][ni][3];
            }
        }
    }
}

// In-place round Weff to tf32 (RNA) so the out-GEMM skips per-fragment cvt.
__global__ void weff_cvt_kernel(float* w) {
    int i = blockIdx.x * blockDim.x + threadIdx.x;   // float4 index
    float4 v = ((float4*)w)[i];
    uint4 u;
    u.x = f2tf(v.x); u.y = f2tf(v.y); u.z = f2tf(v.z); u.w = f2tf(v.w);
    ((uint4*)w)[i] = u;
}

// ---------------------------------------------------------------------------
// Fused middle kernel (unchanged): one CTA per (head, batch).
// ---------------------------------------------------------------------------
__global__ __launch_bounds__(256) void fused_middle(
    const float* __restrict__ Gg, const float* __restrict__ Wq,
    const float* __restrict__ Wk, const float* __restrict__ Wv,
    const float* __restrict__ Wout, float* __restrict__ Weff)
{
    extern __shared__ uint32_t smw[];
    uint32_t* SW  = smw;
    uint32_t* SG  = smw + 18432;
    uint32_t* SQK = smw + 35072;
    float* SMM  = (float*)(smw + 53504);
    float* SATT = (float*)(smw + 54560);
    float* SDQ  = (float*)(smw + 55616);
    float* SDK  = (float*)(smw + 55648);

    const int h = blockIdx.x;
    const int b = blockIdx.z;
    const float* G = Gg + (long)b * CDIM * CDIM;
    float* Wf = Weff + (long)b * CDIM * CDIM;

    const int tid  = threadIdx.x;
    const int lane = tid & 31;
    const int warp = tid >> 5;
    const int g  = lane >> 2;
    const int t4 = lane & 3;

    for (int i = tid; i < 256 * 64; i += 256) {
        int k = i >> 6, n = i & 63;
        float v = (n < 32) ? Wq[k * CDIM + h * 32 + n]
                           : Wk[k * CDIM + h * 32 + (n - 32)];
        SW[k * 72 + n] = f2tf(v);
    }
    __syncthreads();

    const int m0 = (warp & 3) * 16;
    const int n0 = (warp >> 2) * 32;
    for (int mb = 0; mb < 4; mb++) {
        for (int i = tid; i < 4096; i += 256) {
            int row = i >> 6, c4 = (i & 63) << 2;
            float4 v = *(const float4*)(G + (long)(mb * 64 + row) * 256 + c4);
            uint32_t* d = SG + row * 260 + c4;
            d[0] = f2tf(v.x); d[1] = f2tf(v.y); d[2] = f2tf(v.z); d[3] = f2tf(v.w);
        }
        __syncthreads();
        float acc[4][4];
#pragma unroll
        for (int i = 0; i < 4; i++)
#pragma unroll
            for (int r = 0; r < 4; r++) acc[i][r] = 0.f;
#pragma unroll 8
        for (int ks = 0; ks < 256; ks += 8) {
            uint32_t af[4], bf[4][2];
            af[0] = SG[(m0 + g) * 260 + ks + t4];
            af[1] = SG[(m0 + g + 8) * 260 + ks + t4];
            af[2] = SG[(m0 + g) * 260 + ks + t4 + 4];
            af[3] = SG[(m0 + g + 8) * 260 + ks + t4 + 4];
#pragma unroll
            for (int nf = 0; nf < 4; nf++) {
                int nn = n0 + nf * 8;
                bf[nf][0] = SW[(ks + t4) * 72 + nn + g];
                bf[nf][1] = SW[(ks + t4 + 4) * 72 + nn + g];
            }
#pragma unroll
            for (int nf = 0; nf < 4; nf++) mma8(acc[nf], af, bf[nf]);
        }
#pragma unroll
        for (int nf = 0; nf < 4; nf++) {
            int nn = n0 + nf * 8 + t4 * 2;
            int rr = mb * 64 + m0 + g;
            SQK[rr * 72 + nn]       = __float_as_uint(acc[nf][0]);
            SQK[rr * 72 + nn + 1]   = __float_as_uint(acc[nf][1]);
            SQK[(rr + 8) * 72 + nn]     = __float_as_uint(acc[nf][2]);
            SQK[(rr + 8) * 72 + nn + 1] = __float_as_uint(acc[nf][3]);
        }
        __syncthreads();
    }

    {
        int e = tid & 31, cb = warp * 4;
        float a0 = 0.f, a1 = 0.f, a2 = 0.f, a3 = 0.f;
        for (int m = 0; m < 256; m++) {
            float kv = __uint_as_float(SQK[m * 72 + 32 + e]);
            a0 += __uint_as_float(SW[m * 72 + cb + 0]) * kv;
            a1 += __uint_as_float(SW[m * 72 + cb + 1]) * kv;
            a2 += __uint_as_float(SW[m * 72 + cb + 2]) * kv;
            a3 += __uint_as_float(SW[m * 72 + cb + 3]) * kv;
        }
        SMM[(cb + 0) * 33 + e] = a0;
        SMM[(cb + 1) * 33 + e] = a1;
        SMM[(cb + 2) * 33 + e] = a2;
        SMM[(cb + 3) * 33 + e] = a3;
        if (tid < 32) {
            float d = 0.f;
            for (int m = 0; m < 256; m++)
                d += __uint_as_float(SW[m * 72 + tid]) * __uint_as_float(SQK[m * 72 + tid]);
            SDQ[tid] = d;
        } else if (tid < 64) {
            int e2 = tid - 32;
            float d = 0.f;
            for (int m = 0; m < 256; m++)
                d += __uint_as_float(SW[m * 72 + 32 + e2]) * __uint_as_float(SQK[m * 72 + 32 + e2]);
            SDK[e2] = d;
        }
    }
    __syncthreads();

    {
        float nk = rsqrtf(SDK[lane]);
#pragma unroll
        for (int r = 0; r < 4; r++) {
            int c = warp * 4 + r;
            float nq = rsqrtf(SDQ[c]);
            float l = SMM[c * 33 + lane] * nq * nk * (1.0f / 128.0f);
            float mx = l;
            for (int o = 16; o; o >>= 1) mx = fmaxf(mx, __shfl_xor_sync(0xffffffffu, mx, o));
            float p = __expf(l - mx);
            float s = p;
            for (int o = 16; o; o >>= 1) s += __shfl_xor_sync(0xffffffffu, s, o);
            SATT[c * 33 + lane] = p / s;
        }
    }
    __syncthreads();

    uint32_t* SWv = smw;
    uint32_t* SWx = smw + 9216;
    {
        float wo[32];
#pragma unroll
        for (int c = 0; c < 32; c++) wo[c] = Wout[(h * 32 + c) * CDIM + tid];
        for (int e = 0; e < 32; e++) {
            float a = 0.f;
#pragma unroll
            for (int c = 0; c < 32; c++) a += SATT[c * 33 + e] * wo[c];
            SWx[e * 264 + tid] = f2tf(a);
        }
        for (int i = tid; i < 8192; i += 256) {
            int m = i >> 5, e = i & 31;
            SWv[m * 36 + e] = f2tf(Wv[m * CDIM + h * 32 + e]);
        }
    }
    __syncthreads();

    {
        const int m0w = warp * 32;
        for (int nc = 0; nc < 4; nc++) {
            float acc[2][8][4];
#pragma unroll
            for (int mi = 0; mi < 2; mi++)
#pragma unroll
                for (int nf = 0; nf < 8; nf++)
#pragma unroll
                    for (int r = 0; r < 4; r++) acc[mi][nf][r] = 0.f;
#pragma unroll
            for (int ks = 0; ks < 32; ks += 8) {
                uint32_t af[2][4];
#pragma unroll
                for (int mi = 0; mi < 2; mi++) {
                    int mm = m0w + mi * 16;
                    af[mi][0] = SWv[(mm + g) * 36 + ks + t4];
                    af[mi][1] = SWv[(mm + g + 8) * 36 + ks + t4];
                    af[mi][2] = SWv[(mm + g) * 36 + ks + t4 + 4];
                    af[mi][3] = SWv[(mm + g + 8) * 36 + ks + t4 + 4];
                }
#pragma unroll
                for (int nf = 0; nf < 8; nf++) {
                    int nn = nc * 64 + nf * 8 + g;
                    uint32_t bf[2];
                    bf[0] = SWx[(ks + t4) * 264 + nn];
                    bf[1] = SWx[(ks + t4 + 4) * 264 + nn];
                    mma8(acc[0][nf], af[0], bf);
                    mma8(acc[1][nf], af[1], bf);
                }
            }
#pragma unroll
            for (int mi = 0; mi < 2; mi++) {
#pragma unroll
                for (int nf = 0; nf < 8; nf++) {
                    int rr = m0w + mi * 16 + g;
                    int cc = nc * 64 + nf * 8 + t4 * 2;
                    atomicAdd(&Wf[rr * 256 + cc],           acc[mi][nf][0]);
                    atomicAdd(&Wf[rr * 256 + cc + 1],       acc[mi][nf][1]);
                    atomicAdd(&Wf[(rr + 8) * 256 + cc],     acc[mi][nf][2]);
                    atomicAdd(&Wf[(rr + 8) * 256 + cc + 1], acc[mi][nf][3]);
                }
            }
        }
    }
}

// ---------------------------------------------------------------------------
extern "C" void kernel_launch(void* const* d_in, const int* in_sizes, int n_in,
                              void* d_out, int out_size) {
    (void)in_sizes; (void)n_in; (void)out_size;
    const float* x    = (const float*)d_in[0];
    const float* Wq   = (const float*)d_in[1];
    const float* Wk   = (const float*)d_in[2];
    const float* Wv   = (const float*)d_in[3];
    const float* Wout = (const float*)d_in[4];
    float* out = (float*)d_out;

    float *G, *Weff;
    cudaGetSymbolAddress((void**)&G,    g_G);
    cudaGetSymbolAddress((void**)&Weff, g_Weff);

    const long sX = (long)HW * CDIM;
    const long sM = (long)CDIM * CDIM;

    const int smemGram  = 3 * (4352 + 4352) * 4;   // 104448
    const int smemOut   = 3 * (4608 + 4352) * 4;   // 107520
    const int smemFused = 55680 * 4;               // 222720

    cudaFuncSetAttribute(gemm_db<true, true, true, true>,
                         cudaFuncAttributeMaxDynamicSharedMemorySize, smemGram);
    cudaFuncSetAttribute(gemm_db<false, false, false, false>,
                         cudaFuncAttributeMaxDynamicSharedMemorySize, smemOut);
    cudaFuncSetAttribute(fused_middle,
                         cudaFuncAttributeMaxDynamicSharedMemorySize, smemFused);

    cudaMemsetAsync(G,    0, BATCH * CDIM * CDIM * sizeof(float));
    cudaMemsetAsync(Weff, 0, BATCH * CDIM * CDIM * sizeof(float));

    // G[b] = X_b^T X_b  (symmetric: 3 tiles, split-K 32, diagonal B-aliasing)
    {
        dim3 gr(3 * 32, 1, BATCH);
        gemm_db<true, true, true, true><<<gr, 256, smemGram>>>(
            x, x, G, CDIM, CDIM, HW, sX, sX, sM, 512);
    }

    // fused middle
    {
        dim3 gr(HEADS, 1, BATCH);
        fused_middle<<<gr, 256, smemFused>>>(G, Wq, Wk, Wv, Wout, Weff);
    }

    // round Weff to tf32 once (out-GEMM then skips B-fragment cvt)
    weff_cvt_kernel<<<(BATCH * CDIM * CDIM / 4) / 256, 256>>>(Weff);

    // out = X @ Weff
    {
        dim3 gr(128 * 2, 1, BATCH);
        gemm_db<false, false, false, false><<<gr, 256, smemOut>>>(
            x, Weff, out, HW, CDIM, CDIM, sX, sM, sX, CDIM);
    }
}